// round 15
// baseline (speedup 1.0000x reference)
#include <cuda_runtime.h>
#include <cuda_fp16.h>
#include <cstdint>
#include <cstddef>

// ---------------------------------------------------------------------------
// Dual cross-attention (e2s, s2e), fp16 mma.sync (m16n8k16, fp32 accum).
// R15: best-of-measured assembly. Attention = R11 (16 rows/warp, 128-key
// rounds, fp32 ex2; 184us). GEMMs = R9 128x128 gemm_h template for BOTH
// projections and output (non-attn 122-125us measured; 64x128 retiles were
// confounded losses). cvt = one flat launch, zero wasted blocks.
// ---------------------------------------------------------------------------

constexpr int kB = 4;
constexpr int kT = 2048;
constexpr int kD = 512;
constexpr int kH = 8;
constexpr int kDK = 64;
constexpr int kM = kB * kT;  // 8192 rows
constexpr float kSmScale = 1.5f / 8.0f;  // SCALE / sqrt(DK)
constexpr float kLog2e = 1.4426950408889634f;
constexpr uint32_t kOnesH2 = 0x3C003C00u;  // fp16x2 {1.0, 1.0}

__device__ __half g_Q[2 * (size_t)kM * kD];
__device__ __half g_K[2 * (size_t)kM * kD];
__device__ __half g_V[2 * (size_t)kM * kD];
__device__ __half g_O[2 * (size_t)kM * kD];
__device__ __half g_Ah[2 * (size_t)kM * kD];  // fp16 skel | sens
__device__ __half g_Wh[8 * (size_t)kD * kD];  // fp16 weights

struct Batch6 {
  const __half* A[6];
  const __half* W[6];
  void* C[6];
};
struct AttnBatch {
  const __half* Q[2];
  const __half* K[2];
  const __half* V[2];
  const int* M[2];
  __half* O[2];
};
struct CvtBatch {
  const float* act[2];
  const float* w[8];
};

__device__ __forceinline__ uint32_t f2h2(float lo, float hi) {
  uint32_t r;
  asm("cvt.rn.f16x2.f32 %0, %1, %2;" : "=r"(r) : "f"(hi), "f"(lo));
  return r;
}

__device__ __forceinline__ float ex2(float f) {
  float r;
  asm("ex2.approx.ftz.f32 %0, %1;" : "=f"(r) : "f"(f));
  return r;
}

__device__ __forceinline__ uint32_t smem_u32(const void* p) {
  uint32_t a;
  asm("{ .reg .u64 t; cvta.to.shared.u64 t, %1; cvt.u32.u64 %0, t; }"
      : "=r"(a) : "l"(p));
  return a;
}

__device__ __forceinline__ void cpa16(uint32_t dst, const void* src) {
  asm volatile("cp.async.cg.shared.global [%0], [%1], 16;"
               :: "r"(dst), "l"(src));
}
#define CP_COMMIT() asm volatile("cp.async.commit_group;" ::: "memory")
#define CP_WAIT0() asm volatile("cp.async.wait_group 0;" ::: "memory")

// D += A(16x16) * B(16x8), fp16 in, fp32 accum.
__device__ __forceinline__ void mma16(float* d, const uint32_t* a, uint32_t b0,
                                      uint32_t b1) {
  asm volatile(
      "mma.sync.aligned.m16n8k16.row.col.f32.f16.f16.f32 "
      "{%0,%1,%2,%3}, {%4,%5,%6,%7}, {%8,%9}, {%0,%1,%2,%3};\n"
      : "+f"(d[0]), "+f"(d[1]), "+f"(d[2]), "+f"(d[3])
      : "r"(a[0]), "r"(a[1]), "r"(a[2]), "r"(a[3]), "r"(b0), "r"(b1));
}

__device__ __forceinline__ void ldsm4(uint32_t& r0, uint32_t& r1, uint32_t& r2,
                                      uint32_t& r3, uint32_t addr) {
  asm volatile(
      "ldmatrix.sync.aligned.m8n8.x4.shared.b16 {%0,%1,%2,%3}, [%4];"
      : "=r"(r0), "=r"(r1), "=r"(r2), "=r"(r3) : "r"(addr));
}

__device__ __forceinline__ void ldsm4t(uint32_t& r0, uint32_t& r1,
                                       uint32_t& r2, uint32_t& r3,
                                       uint32_t addr) {
  asm volatile(
      "ldmatrix.sync.aligned.m8n8.x4.trans.shared.b16 {%0,%1,%2,%3}, [%4];"
      : "=r"(r0), "=r"(r1), "=r"(r2), "=r"(r3) : "r"(addr));
}

// ---------------------------------------------------------------------------
// One-time fp32 -> fp16 conversion, flat 1-D grid, zero wasted blocks.
// Granule layout: [0, 2*actN4) = activations, then 8 x wN4 weights.
// ---------------------------------------------------------------------------
constexpr int kActN4 = kM * kD / 4;   // 1,048,576 granules per activation
constexpr int kWN4 = kD * kD / 4;     // 65,536 granules per weight
constexpr int kCvtTotal = 2 * kActN4 + 8 * kWN4;  // 2,621,440

__global__ void cvt_all(CvtBatch cb) {
  int idx = blockIdx.x * blockDim.x + threadIdx.x;
  const float* src;
  __half* dst;
  int within;
  if (idx < 2 * kActN4) {
    int t = idx >> 20;            // kActN4 = 2^20
    within = idx & (kActN4 - 1);
    src = cb.act[t];
    dst = g_Ah + (size_t)t * kM * kD;
  } else {
    int wb = idx - 2 * kActN4;
    int t = wb >> 16;             // kWN4 = 2^16
    within = wb & (kWN4 - 1);
    src = cb.w[t];
    dst = g_Wh + (size_t)t * kD * kD;
  }
  float4 v = reinterpret_cast<const float4*>(src)[within];
  reinterpret_cast<uint2*>(dst)[within] =
      make_uint2(f2h2(v.x, v.y), f2h2(v.z, v.w));
}

// ---------------------------------------------------------------------------
// Batched C = A @ W^T, 128x128 tiles, 8 warps = 4(M) x 2(N), 2 CTAs/SM.
// 2-stage cp.async, ldmatrix.x4 fragments. (R9, proven best for both roles)
// Smem words: sA[2][128*36]@0, sB[2][128*36]@9216 -> 18432 w.
// ---------------------------------------------------------------------------
constexpr int kGemmSmem = 18432 * 4;

template <bool OUT_HALF>
__global__ void __launch_bounds__(256, 2)
    gemm_h(Batch6 b) {
  extern __shared__ uint32_t gsm[];

  const __half* __restrict__ A = b.A[blockIdx.z];
  const __half* __restrict__ W = b.W[blockIdx.z];
  void* Cp = b.C[blockIdx.z];

  const int tid = threadIdx.x;
  const int lane = tid & 31;
  const int wid = tid >> 5;
  const int wm = wid & 3;
  const int wn = wid >> 2;
  const int g = lane >> 2;
  const int tg = lane & 3;
  const int m0 = blockIdx.x * 128;
  const int n0 = blockIdx.y * 128;

  const uint32_t sAb = smem_u32(gsm);
  const uint32_t sBb = sAb + 9216 * 4;

  const int a_row = ((lane >> 3) & 1) * 8 + (lane & 7);
  const int a_col = (lane >> 4) * 4;
  const int b_row = (lane >> 4) * 8 + (lane & 7);
  const int b_col = ((lane >> 3) & 1) * 4;

  float acc[2][8][4];
#pragma unroll
  for (int mi = 0; mi < 2; ++mi)
#pragma unroll
    for (int ni = 0; ni < 8; ++ni)
#pragma unroll
      for (int c = 0; c < 4; ++c) acc[mi][ni][c] = 0.f;

  auto stage = [&](int kt, int buf) {
#pragma unroll
    for (int it = 0; it < 4; ++it) {
      int task = it * 256 + tid;  // row(7b) x granule(3b)
      int row = task >> 3;
      int gr = task & 7;
      cpa16(sAb + (buf * 4608 + row * 36 + gr * 4) * 4,
            A + (size_t)(m0 + row) * kD + kt * 64 + gr * 8);
      cpa16(sBb + (buf * 4608 + row * 36 + gr * 4) * 4,
            W + (size_t)(n0 + row) * kD + kt * 64 + gr * 8);
    }
    CP_COMMIT();
  };

  stage(0, 0);
  CP_WAIT0();
  __syncthreads();

  for (int kt = 0; kt < 8; ++kt) {
    const int p = kt & 1;
    if (kt < 7) stage(kt + 1, 1 - p);
    const uint32_t sAp = sAb + p * 4608 * 4;
    const uint32_t sBp = sBb + p * 4608 * 4;
#pragma unroll
    for (int kk = 0; kk < 4; ++kk) {
      uint32_t a[2][4];
#pragma unroll
      for (int mi = 0; mi < 2; ++mi) {
        uint32_t addr =
            sAp + (((wm * 32 + mi * 16 + a_row) * 36) + kk * 8 + a_col) * 4;
        ldsm4(a[mi][0], a[mi][1], a[mi][2], a[mi][3], addr);
      }
#pragma unroll
      for (int ni2 = 0; ni2 < 4; ++ni2) {
        uint32_t b0, b1, b2, b3;
        uint32_t addr =
            sBp + (((wn * 64 + ni2 * 16 + b_row) * 36) + kk * 8 + b_col) * 4;
        ldsm4(b0, b1, b2, b3, addr);
        mma16(acc[0][2 * ni2], a[0], b0, b1);
        mma16(acc[0][2 * ni2 + 1], a[0], b2, b3);
        mma16(acc[1][2 * ni2], a[1], b0, b1);
        mma16(acc[1][2 * ni2 + 1], a[1], b2, b3);
      }
    }
    CP_WAIT0();
    __syncthreads();
  }

#pragma unroll
  for (int mi = 0; mi < 2; ++mi) {
    int row = m0 + wm * 32 + mi * 16 + g;
#pragma unroll
    for (int ni = 0; ni < 8; ++ni) {
      int col = n0 + wn * 64 + ni * 8 + 2 * tg;
      if (OUT_HALF) {
        uint32_t* Ch = (uint32_t*)Cp;  // half2 view
        Ch[(size_t)row * 256 + (col >> 1)] =
            f2h2(acc[mi][ni][0], acc[mi][ni][1]);
        Ch[(size_t)(row + 8) * 256 + (col >> 1)] =
            f2h2(acc[mi][ni][2], acc[mi][ni][3]);
      } else {
        float* Cf = (float*)Cp;
        *reinterpret_cast<float2*>(Cf + (size_t)row * kD + col) =
            make_float2(acc[mi][ni][0], acc[mi][ni][1]);
        *reinterpret_cast<float2*>(Cf + (size_t)(row + 8) * kD + col) =
            make_float2(acc[mi][ni][2], acc[mi][ni][3]);
      }
    }
  }
}

// ---------------------------------------------------------------------------
// Flash attention, fp16, batched; 8 warps x 16 query rows; 128-key staging
// rounds, two 64-key compute halves; fp32 ex2. (R11, measured 184us)
// SMEM words: sK[2][128*36]@0, sV[2][128*36]@9216, sQ[128*36]@18432,
// bias[2][128]@23040. Total 23296 w = 93184 B.
// ---------------------------------------------------------------------------
constexpr int kOffK = 0;
constexpr int kOffV = 9216;
constexpr int kOffQ = 18432;
constexpr int kOffBias = 23040;
constexpr int kAttnSmem = 23296 * 4;
constexpr int kNRounds = kT / 128;  // 16

__global__ void __launch_bounds__(256, 2)
    attn_f16(AttnBatch ab) {
  extern __shared__ uint32_t asm_[];
  float* sBias = reinterpret_cast<float*>(asm_ + kOffBias);

  const int which = blockIdx.z >> 2;
  const int bb = blockIdx.z & 3;
  const __half* __restrict__ Qg = ab.Q[which];
  const __half* __restrict__ Kg = ab.K[which];
  const __half* __restrict__ Vg = ab.V[which];
  const int* __restrict__ mask = ab.M[which];
  __half* __restrict__ Og = ab.O[which];

  const int tid = threadIdx.x;
  const int lane = tid & 31;
  const int w = tid >> 5;
  const int g = lane >> 2;
  const int tg = lane & 3;
  const int h = blockIdx.y;
  const int q0 = blockIdx.x * 128;
  const int colh = h * kDK;
  const size_t qrow0 = (size_t)bb * kT + q0;
  const size_t kvrow0 = (size_t)bb * kT;
  const int w16 = w * 16;

  const uint32_t smem_base = smem_u32(asm_);
  const uint32_t skb = smem_base + kOffK * 4;
  const uint32_t svb = smem_base + kOffV * 4;
  const uint32_t sqb = smem_base + kOffQ * 4;

  // ldmatrix lane constants
  const int kb_row = (lane >> 4) * 8 + (lane & 7);        // non-trans B (K)
  const int kb_col = ((lane >> 3) & 1) * 4;
  const int lm_row = ((lane >> 3) & 1) * 8 + (lane & 7);  // trans (V)
  const int lm_col = (lane >> 4) * 4;

  // stage one 128-key round into buffer buf
  auto stage_async = [&](int r, int buf) {
#pragma unroll
    for (int it = 0; it < 4; ++it) {
      int task = it * 256 + tid;  // row(7b) x granule(3b)
      int row = task >> 3;
      int gr = task & 7;
      const __half* ks = Kg + (kvrow0 + r * 128 + row) * kD + colh + gr * 8;
      const __half* vs = Vg + (kvrow0 + r * 128 + row) * kD + colh + gr * 8;
      cpa16(skb + (buf * 4608 + row * 36 + gr * 4) * 4, ks);
      cpa16(svb + (buf * 4608 + row * 36 + gr * 4) * 4, vs);
    }
    if (tid < 128)
      sBias[buf * 128 + tid] =
          mask[kvrow0 + r * 128 + tid] ? 0.f : -1.4426950e30f;
    CP_COMMIT();
  };

  // ---- stage Q (128x64) + round 0 ----
#pragma unroll
  for (int it = 0; it < 4; ++it) {
    int task = it * 256 + tid;
    int row = task >> 3;
    int gr = task & 7;
    cpa16(sqb + (row * 36 + gr * 4) * 4,
          Qg + (qrow0 + row) * kD + colh + gr * 8);
  }
  CP_COMMIT();
  stage_async(0, 0);
  CP_WAIT0();
  __syncthreads();

  // ---- lift Q A-fragments ----
  const uint32_t* sQ = asm_ + kOffQ;
  uint32_t aq[4][4];
#pragma unroll
  for (int kk = 0; kk < 4; ++kk) {
    aq[kk][0] = sQ[(w16 + g) * 36 + kk * 8 + tg];
    aq[kk][1] = sQ[(w16 + g + 8) * 36 + kk * 8 + tg];
    aq[kk][2] = sQ[(w16 + g) * 36 + kk * 8 + tg + 4];
    aq[kk][3] = sQ[(w16 + g + 8) * 36 + kk * 8 + tg + 4];
  }

  float o[8][4];
#pragma unroll
  for (int ni = 0; ni < 8; ++ni)
#pragma unroll
    for (int c = 0; c < 4; ++c) o[ni][c] = 0.f;
  float lacc[4] = {0.f, 0.f, 0.f, 0.f};
  const float sc = kSmScale * kLog2e;

  for (int r = 0; r < kNRounds; ++r) {
    const int p = r & 1;

#pragma unroll
    for (int half = 0; half < 2; ++half) {
      const uint32_t skbase = skb + (p * 4608 + half * 64 * 36) * 4;
      const uint32_t svbase = svb + (p * 4608 + half * 64 * 36) * 4;
      const float* bias = sBias + p * 128 + half * 64;

      // ---- S = Q K^T (64-key half) ----
      float s[8][4];
#pragma unroll
      for (int ni = 0; ni < 8; ++ni)
#pragma unroll
        for (int c = 0; c < 4; ++c) s[ni][c] = 0.f;
#pragma unroll
      for (int kk = 0; kk < 4; ++kk)
#pragma unroll
        for (int ni2 = 0; ni2 < 4; ++ni2) {
          uint32_t b0, b1, b2, b3;
          uint32_t addr =
              skbase + (((ni2 * 16 + kb_row) * 36) + kk * 8 + kb_col) * 4;
          ldsm4(b0, b1, b2, b3, addr);
          mma16(s[2 * ni2], aq[kk], b0, b1);
          mma16(s[2 * ni2 + 1], aq[kk], b2, b3);
        }

      // kick next round's staging once, right after the first half's S
      if (half == 0 && r + 1 < kNRounds) stage_async(r + 1, 1 - p);

      // ---- p = exp2(s*sc + bias) (fp32 ex2; no max subtraction) ----
#pragma unroll
      for (int ni = 0; ni < 8; ++ni) {
        float bb0 = bias[ni * 8 + 2 * tg];
        float bb1 = bias[ni * 8 + 2 * tg + 1];
        s[ni][0] = ex2(s[ni][0] * sc + bb0);
        s[ni][1] = ex2(s[ni][1] * sc + bb1);
        s[ni][2] = ex2(s[ni][2] * sc + bb0);
        s[ni][3] = ex2(s[ni][3] * sc + bb1);
      }

      // ---- O += P V ; l += P @ ones ----
#pragma unroll
      for (int kkp = 0; kkp < 4; ++kkp) {
        uint32_t pa[4];
        pa[0] = f2h2(s[2 * kkp][0], s[2 * kkp][1]);
        pa[1] = f2h2(s[2 * kkp][2], s[2 * kkp][3]);
        pa[2] = f2h2(s[2 * kkp + 1][0], s[2 * kkp + 1][1]);
        pa[3] = f2h2(s[2 * kkp + 1][2], s[2 * kkp + 1][3]);
        mma16(lacc, pa, kOnesH2, kOnesH2);
#pragma unroll
        for (int nip = 0; nip < 4; ++nip) {
          uint32_t v0, v1, v2, v3;
          uint32_t addr =
              svbase + (((16 * kkp + lm_row) * 36) + nip * 8 + lm_col) * 4;
          ldsm4t(v0, v1, v2, v3, addr);
          mma16(o[2 * nip], pa, v0, v1);
          mma16(o[2 * nip + 1], pa, v2, v3);
        }
      }
    }

    // ---- next round's copies done + visible ----
    CP_WAIT0();
    __syncthreads();
  }

  // ---- normalize, store O (fp16) ----
  const float inv0 = 1.f / lacc[0];
  const float inv1 = 1.f / lacc[2];
  uint32_t* Oh = reinterpret_cast<uint32_t*>(Og);  // half2 view
#pragma unroll
  for (int ni = 0; ni < 8; ++ni) {
    size_t idx = (qrow0 + w16 + g) * 256 + ((colh + ni * 8) >> 1) + tg;
    Oh[idx] = f2h2(o[ni][0] * inv0, o[ni][1] * inv0);
    Oh[idx + 8 * 256] = f2h2(o[ni][2] * inv1, o[ni][3] * inv1);
  }
}

// ---------------------------------------------------------------------------
extern "C" void kernel_launch(void* const* d_in, const int* in_sizes, int n_in,
                              void* d_out, int out_size) {
  const float* skel = (const float*)d_in[0];
  const float* sens = (const float*)d_in[1];
  const int* mask_skel = (const int*)d_in[2];
  const int* mask_sens = (const int*)d_in[3];
  const float* Wq_s2e = (const float*)d_in[4];
  const float* Wk_e = (const float*)d_in[5];
  const float* Wv_e = (const float*)d_in[6];
  const float* Wq_e2s = (const float*)d_in[7];
  const float* Wk_s = (const float*)d_in[8];
  const float* Wv_s = (const float*)d_in[9];
  const float* Wo_s = (const float*)d_in[10];
  const float* Wo_e = (const float*)d_in[11];

  float* out_e2s = (float*)d_out;                     // tuple element 0
  float* out_s2e = (float*)d_out + (size_t)kM * kD;   // tuple element 1

  __half *Qp, *Kp, *Vp, *Op, *Ah, *Wh;
  cudaGetSymbolAddress((void**)&Qp, g_Q);
  cudaGetSymbolAddress((void**)&Kp, g_K);
  cudaGetSymbolAddress((void**)&Vp, g_V);
  cudaGetSymbolAddress((void**)&Op, g_O);
  cudaGetSymbolAddress((void**)&Ah, g_Ah);
  cudaGetSymbolAddress((void**)&Wh, g_Wh);

  cudaFuncSetAttribute(attn_f16, cudaFuncAttributeMaxDynamicSharedMemorySize,
                       kAttnSmem);
  cudaFuncSetAttribute(gemm_h<true>,
                       cudaFuncAttributeMaxDynamicSharedMemorySize, kGemmSmem);
  cudaFuncSetAttribute(gemm_h<false>,
                       cudaFuncAttributeMaxDynamicSharedMemorySize, kGemmSmem);

  const size_t off = (size_t)kM * kD;
  const __half* skel_h = Ah;
  const __half* sens_h = Ah + off;
  auto Wp = [&](int i) { return (const __half*)(Wh + (size_t)i * kD * kD); };
  // order: 0 Wq_s2e, 1 Wk_e, 2 Wv_e, 3 Wq_e2s, 4 Wk_s, 5 Wv_s, 6 Wo_s, 7 Wo_e

  // ---- one-time conversions: single flat launch, zero wasted blocks ----
  {
    CvtBatch cb;
    cb.act[0] = skel;
    cb.act[1] = sens;
    const float* ws[8] = {Wq_s2e, Wk_e, Wv_e, Wq_e2s, Wk_s, Wv_s, Wo_s, Wo_e};
    for (int i = 0; i < 8; ++i) cb.w[i] = ws[i];
    cvt_all<<<kCvtTotal / 256, 256>>>(cb);
  }

  // ---- batched projections: set0 = s2e (Q,K,V), set1 = e2s (Q,K,V) ----
  Batch6 proj;
  proj.A[0] = skel_h; proj.W[0] = Wp(0); proj.C[0] = Qp;
  proj.A[1] = sens_h; proj.W[1] = Wp(1); proj.C[1] = Kp;
  proj.A[2] = sens_h; proj.W[2] = Wp(2); proj.C[2] = Vp;
  proj.A[3] = sens_h; proj.W[3] = Wp(3); proj.C[3] = Qp + off;
  proj.A[4] = skel_h; proj.W[4] = Wp(4); proj.C[4] = Kp + off;
  proj.A[5] = skel_h; proj.W[5] = Wp(5); proj.C[5] = Vp + off;
  gemm_h<true><<<dim3(kM / 128, kD / 128, 6), 256, kGemmSmem>>>(proj);

  // ---- batched attentions ----
  AttnBatch ab;
  ab.Q[0] = Qp;        ab.K[0] = Kp;        ab.V[0] = Vp;
  ab.M[0] = mask_sens; ab.O[0] = Op;
  ab.Q[1] = Qp + off;  ab.K[1] = Kp + off;  ab.V[1] = Vp + off;
  ab.M[1] = mask_skel; ab.O[1] = Op + off;
  attn_f16<<<dim3(kT / 128, kH, 2 * kB), 256, kAttnSmem>>>(ab);

  // ---- batched output projections (128x128 tiles, fp32 out) ----
  Batch6 outb;
  outb.A[0] = Op;       outb.W[0] = Wp(7); outb.C[0] = out_s2e;
  outb.A[1] = Op + off; outb.W[1] = Wp(6); outb.C[1] = out_e2s;
  outb.A[2] = outb.A[3] = outb.A[4] = outb.A[5] = Op;
  outb.W[2] = outb.W[3] = outb.W[4] = outb.W[5] = Wp(7);
  outb.C[2] = outb.C[3] = outb.C[4] = outb.C[5] = nullptr;  // unused
  gemm_h<false><<<dim3(kM / 128, kD / 128, 2), 256, kGemmSmem>>>(outb);
}

// round 16
// speedup vs baseline: 1.0391x; 1.0391x over previous
#include <cuda_runtime.h>
#include <cuda_fp16.h>
#include <cstdint>
#include <cstddef>

// ---------------------------------------------------------------------------
// Dual cross-attention (e2s, s2e), fp16 mma.sync (m16n8k16, fp32 accum).
// R16 == R11 exactly (session-best measured 313.8us): attention with 16
// rows/warp, 128-key staging rounds split into two 64-key compute halves,
// fp32 ex2, no-max softmax, mma row-sum; proj GEMM 128x128 @ 2 CTAs/SM;
// out GEMM 64x128 @ 3 CTAs/SM; two-launch one-time fp16 conversion.
// ---------------------------------------------------------------------------

constexpr int kB = 4;
constexpr int kT = 2048;
constexpr int kD = 512;
constexpr int kH = 8;
constexpr int kDK = 64;
constexpr int kM = kB * kT;  // 8192 rows
constexpr float kSmScale = 1.5f / 8.0f;  // SCALE / sqrt(DK)
constexpr float kLog2e = 1.4426950408889634f;
constexpr uint32_t kOnesH2 = 0x3C003C00u;  // fp16x2 {1.0, 1.0}

__device__ __half g_Q[2 * (size_t)kM * kD];
__device__ __half g_K[2 * (size_t)kM * kD];
__device__ __half g_V[2 * (size_t)kM * kD];
__device__ __half g_O[2 * (size_t)kM * kD];
__device__ __half g_Ah[2 * (size_t)kM * kD];  // fp16 skel | sens
__device__ __half g_Wh[8 * (size_t)kD * kD];  // fp16 weights

struct Batch6 {
  const __half* A[6];
  const __half* W[6];
  void* C[6];
};
struct Batch2 {
  const __half* A[2];
  const __half* W[2];
  float* C[2];
};
struct AttnBatch {
  const __half* Q[2];
  const __half* K[2];
  const __half* V[2];
  const int* M[2];
  __half* O[2];
};

__device__ __forceinline__ uint32_t f2h2(float lo, float hi) {
  uint32_t r;
  asm("cvt.rn.f16x2.f32 %0, %1, %2;" : "=r"(r) : "f"(hi), "f"(lo));
  return r;
}

__device__ __forceinline__ float ex2(float f) {
  float r;
  asm("ex2.approx.ftz.f32 %0, %1;" : "=f"(r) : "f"(f));
  return r;
}

__device__ __forceinline__ uint32_t smem_u32(const void* p) {
  uint32_t a;
  asm("{ .reg .u64 t; cvta.to.shared.u64 t, %1; cvt.u32.u64 %0, t; }"
      : "=r"(a) : "l"(p));
  return a;
}

__device__ __forceinline__ void cpa16(uint32_t dst, const void* src) {
  asm volatile("cp.async.cg.shared.global [%0], [%1], 16;"
               :: "r"(dst), "l"(src));
}
#define CP_COMMIT() asm volatile("cp.async.commit_group;" ::: "memory")
#define CP_WAIT0() asm volatile("cp.async.wait_group 0;" ::: "memory")

// D += A(16x16) * B(16x8), fp16 in, fp32 accum.
__device__ __forceinline__ void mma16(float* d, const uint32_t* a, uint32_t b0,
                                      uint32_t b1) {
  asm volatile(
      "mma.sync.aligned.m16n8k16.row.col.f32.f16.f16.f32 "
      "{%0,%1,%2,%3}, {%4,%5,%6,%7}, {%8,%9}, {%0,%1,%2,%3};\n"
      : "+f"(d[0]), "+f"(d[1]), "+f"(d[2]), "+f"(d[3])
      : "r"(a[0]), "r"(a[1]), "r"(a[2]), "r"(a[3]), "r"(b0), "r"(b1));
}

__device__ __forceinline__ void ldsm4(uint32_t& r0, uint32_t& r1, uint32_t& r2,
                                      uint32_t& r3, uint32_t addr) {
  asm volatile(
      "ldmatrix.sync.aligned.m8n8.x4.shared.b16 {%0,%1,%2,%3}, [%4];"
      : "=r"(r0), "=r"(r1), "=r"(r2), "=r"(r3) : "r"(addr));
}

__device__ __forceinline__ void ldsm4t(uint32_t& r0, uint32_t& r1,
                                       uint32_t& r2, uint32_t& r3,
                                       uint32_t addr) {
  asm volatile(
      "ldmatrix.sync.aligned.m8n8.x4.trans.shared.b16 {%0,%1,%2,%3}, [%4];"
      : "=r"(r0), "=r"(r1), "=r"(r2), "=r"(r3) : "r"(addr));
}

// ---------------------------------------------------------------------------
// One-time fp32 -> fp16 conversions.
// ---------------------------------------------------------------------------
__global__ void cvt_act(const float* __restrict__ a0,
                        const float* __restrict__ a1, __half* __restrict__ o) {
  const float* src = blockIdx.y ? a1 : a0;
  uint2* dst = reinterpret_cast<uint2*>(o + (size_t)blockIdx.y * kM * kD);
  int idx = blockIdx.x * blockDim.x + threadIdx.x;  // float4 granules
  float4 v = reinterpret_cast<const float4*>(src)[idx];
  dst[idx] = make_uint2(f2h2(v.x, v.y), f2h2(v.z, v.w));
}

__global__ void cvt_w(const float* w0, const float* w1, const float* w2,
                      const float* w3, const float* w4, const float* w5,
                      const float* w6, const float* w7,
                      __half* __restrict__ o) {
  const float* srcs[8] = {w0, w1, w2, w3, w4, w5, w6, w7};
  const float* src = srcs[blockIdx.y];
  uint2* dst = reinterpret_cast<uint2*>(o + (size_t)blockIdx.y * kD * kD);
  int idx = blockIdx.x * blockDim.x + threadIdx.x;
  float4 v = reinterpret_cast<const float4*>(src)[idx];
  dst[idx] = make_uint2(f2h2(v.x, v.y), f2h2(v.z, v.w));
}

// ---------------------------------------------------------------------------
// Batched C = A @ W^T (fp16 out), 128x128 tiles (R9, proven).
// ---------------------------------------------------------------------------
constexpr int kGemmSmem = 18432 * 4;

__global__ void __launch_bounds__(256, 2)
    gemm_h(Batch6 b) {
  extern __shared__ uint32_t gsm[];

  const __half* __restrict__ A = b.A[blockIdx.z];
  const __half* __restrict__ W = b.W[blockIdx.z];
  void* Cp = b.C[blockIdx.z];

  const int tid = threadIdx.x;
  const int lane = tid & 31;
  const int wid = tid >> 5;
  const int wm = wid & 3;
  const int wn = wid >> 2;
  const int g = lane >> 2;
  const int tg = lane & 3;
  const int m0 = blockIdx.x * 128;
  const int n0 = blockIdx.y * 128;

  const uint32_t sAb = smem_u32(gsm);
  const uint32_t sBb = sAb + 9216 * 4;

  const int a_row = ((lane >> 3) & 1) * 8 + (lane & 7);
  const int a_col = (lane >> 4) * 4;
  const int b_row = (lane >> 4) * 8 + (lane & 7);
  const int b_col = ((lane >> 3) & 1) * 4;

  float acc[2][8][4];
#pragma unroll
  for (int mi = 0; mi < 2; ++mi)
#pragma unroll
    for (int ni = 0; ni < 8; ++ni)
#pragma unroll
      for (int c = 0; c < 4; ++c) acc[mi][ni][c] = 0.f;

  auto stage = [&](int kt, int buf) {
#pragma unroll
    for (int it = 0; it < 4; ++it) {
      int task = it * 256 + tid;  // row(7b) x granule(3b)
      int row = task >> 3;
      int gr = task & 7;
      cpa16(sAb + (buf * 4608 + row * 36 + gr * 4) * 4,
            A + (size_t)(m0 + row) * kD + kt * 64 + gr * 8);
      cpa16(sBb + (buf * 4608 + row * 36 + gr * 4) * 4,
            W + (size_t)(n0 + row) * kD + kt * 64 + gr * 8);
    }
    CP_COMMIT();
  };

  stage(0, 0);
  CP_WAIT0();
  __syncthreads();

  for (int kt = 0; kt < 8; ++kt) {
    const int p = kt & 1;
    if (kt < 7) stage(kt + 1, 1 - p);
    const uint32_t sAp = sAb + p * 4608 * 4;
    const uint32_t sBp = sBb + p * 4608 * 4;
#pragma unroll
    for (int kk = 0; kk < 4; ++kk) {
      uint32_t a[2][4];
#pragma unroll
      for (int mi = 0; mi < 2; ++mi) {
        uint32_t addr =
            sAp + (((wm * 32 + mi * 16 + a_row) * 36) + kk * 8 + a_col) * 4;
        ldsm4(a[mi][0], a[mi][1], a[mi][2], a[mi][3], addr);
      }
#pragma unroll
      for (int ni2 = 0; ni2 < 4; ++ni2) {
        uint32_t b0, b1, b2, b3;
        uint32_t addr =
            sBp + (((wn * 64 + ni2 * 16 + b_row) * 36) + kk * 8 + b_col) * 4;
        ldsm4(b0, b1, b2, b3, addr);
        mma16(acc[0][2 * ni2], a[0], b0, b1);
        mma16(acc[0][2 * ni2 + 1], a[0], b2, b3);
        mma16(acc[1][2 * ni2], a[1], b0, b1);
        mma16(acc[1][2 * ni2 + 1], a[1], b2, b3);
      }
    }
    CP_WAIT0();
    __syncthreads();
  }

#pragma unroll
  for (int mi = 0; mi < 2; ++mi) {
    int row = m0 + wm * 32 + mi * 16 + g;
#pragma unroll
    for (int ni = 0; ni < 8; ++ni) {
      int col = n0 + wn * 64 + ni * 8 + 2 * tg;
      uint32_t* Ch = (uint32_t*)Cp;  // half2 view
      Ch[(size_t)row * 256 + (col >> 1)] =
          f2h2(acc[mi][ni][0], acc[mi][ni][1]);
      Ch[(size_t)(row + 8) * 256 + (col >> 1)] =
          f2h2(acc[mi][ni][2], acc[mi][ni][3]);
    }
  }
}

// ---------------------------------------------------------------------------
// Output projection: C(fp32) = A(fp16) @ W(fp16)^T, 64x128 tiles for tail
// balance. 8 warps = 2(M) x 4(N), warp tile 32x32. 3 CTAs/SM.
// Smem words: sA[2][64*36]@0, sB[2][128*36]@4608 -> 13824 w = 55296 B.
// ---------------------------------------------------------------------------
constexpr int kGemm64Smem = 13824 * 4;

__global__ void __launch_bounds__(256, 3)
    gemm64_f32(Batch2 b) {
  extern __shared__ uint32_t gsm[];

  const __half* __restrict__ A = b.A[blockIdx.z];
  const __half* __restrict__ W = b.W[blockIdx.z];
  float* __restrict__ Cf = b.C[blockIdx.z];

  const int tid = threadIdx.x;
  const int lane = tid & 31;
  const int wid = tid >> 5;
  const int wm = wid & 1;
  const int wn = wid >> 1;  // 0..3
  const int g = lane >> 2;
  const int tg = lane & 3;
  const int m0 = blockIdx.x * 64;
  const int n0 = blockIdx.y * 128;

  const uint32_t sAb = smem_u32(gsm);
  const uint32_t sBb = sAb + 4608 * 4;

  const int a_row = ((lane >> 3) & 1) * 8 + (lane & 7);
  const int a_col = (lane >> 4) * 4;
  const int b_row = (lane >> 4) * 8 + (lane & 7);
  const int b_col = ((lane >> 3) & 1) * 4;

  float acc[2][4][4];
#pragma unroll
  for (int mi = 0; mi < 2; ++mi)
#pragma unroll
    for (int ni = 0; ni < 4; ++ni)
#pragma unroll
      for (int c = 0; c < 4; ++c) acc[mi][ni][c] = 0.f;

  auto stage = [&](int kt, int buf) {
#pragma unroll
    for (int it = 0; it < 2; ++it) {  // A: 64 rows x 8 granules = 512 tasks
      int task = it * 256 + tid;
      int row = task >> 3;
      int gr = task & 7;
      cpa16(sAb + (buf * 2304 + row * 36 + gr * 4) * 4,
            A + (size_t)(m0 + row) * kD + kt * 64 + gr * 8);
    }
#pragma unroll
    for (int it = 0; it < 4; ++it) {  // B: 128 rows x 8 granules = 1024 tasks
      int task = it * 256 + tid;
      int row = task >> 3;
      int gr = task & 7;
      cpa16(sBb + (buf * 4608 + row * 36 + gr * 4) * 4,
            W + (size_t)(n0 + row) * kD + kt * 64 + gr * 8);
    }
    CP_COMMIT();
  };

  stage(0, 0);
  CP_WAIT0();
  __syncthreads();

  for (int kt = 0; kt < 8; ++kt) {
    const int p = kt & 1;
    if (kt < 7) stage(kt + 1, 1 - p);
    const uint32_t sAp = sAb + p * 2304 * 4;
    const uint32_t sBp = sBb + p * 4608 * 4;
#pragma unroll
    for (int kk = 0; kk < 4; ++kk) {
      uint32_t a[2][4];
#pragma unroll
      for (int mi = 0; mi < 2; ++mi) {
        uint32_t addr =
            sAp + (((wm * 32 + mi * 16 + a_row) * 36) + kk * 8 + a_col) * 4;
        ldsm4(a[mi][0], a[mi][1], a[mi][2], a[mi][3], addr);
      }
#pragma unroll
      for (int ni2 = 0; ni2 < 2; ++ni2) {
        uint32_t b0, b1, b2, b3;
        uint32_t addr =
            sBp + (((wn * 32 + ni2 * 16 + b_row) * 36) + kk * 8 + b_col) * 4;
        ldsm4(b0, b1, b2, b3, addr);
        mma16(acc[0][2 * ni2], a[0], b0, b1);
        mma16(acc[0][2 * ni2 + 1], a[0], b2, b3);
        mma16(acc[1][2 * ni2], a[1], b0, b1);
        mma16(acc[1][2 * ni2 + 1], a[1], b2, b3);
      }
    }
    CP_WAIT0();
    __syncthreads();
  }

#pragma unroll
  for (int mi = 0; mi < 2; ++mi) {
    int row = m0 + wm * 32 + mi * 16 + g;
#pragma unroll
    for (int ni = 0; ni < 4; ++ni) {
      int col = n0 + wn * 32 + ni * 8 + 2 * tg;
      *reinterpret_cast<float2*>(Cf + (size_t)row * kD + col) =
          make_float2(acc[mi][ni][0], acc[mi][ni][1]);
      *reinterpret_cast<float2*>(Cf + (size_t)(row + 8) * kD + col) =
          make_float2(acc[mi][ni][2], acc[mi][ni][3]);
    }
  }
}

// ---------------------------------------------------------------------------
// Flash attention, fp16, batched; 8 warps x 16 query rows (R9 shape).
// 128-key staging rounds, each computed as two 64-key halves -> half the
// barriers and a full round of compute under each cp.async batch.
// SMEM words: sK[2][128*36]@0, sV[2][128*36]@9216, sQ[128*36]@18432,
// bias[2][128]@23040. Total 23296 w = 93184 B.
// ---------------------------------------------------------------------------
constexpr int kOffK = 0;
constexpr int kOffV = 9216;
constexpr int kOffQ = 18432;
constexpr int kOffBias = 23040;
constexpr int kAttnSmem = 23296 * 4;
constexpr int kNRounds = kT / 128;  // 16

__global__ void __launch_bounds__(256, 2)
    attn_f16(AttnBatch ab) {
  extern __shared__ uint32_t asm_[];
  float* sBias = reinterpret_cast<float*>(asm_ + kOffBias);

  const int which = blockIdx.z >> 2;
  const int bb = blockIdx.z & 3;
  const __half* __restrict__ Qg = ab.Q[which];
  const __half* __restrict__ Kg = ab.K[which];
  const __half* __restrict__ Vg = ab.V[which];
  const int* __restrict__ mask = ab.M[which];
  __half* __restrict__ Og = ab.O[which];

  const int tid = threadIdx.x;
  const int lane = tid & 31;
  const int w = tid >> 5;
  const int g = lane >> 2;
  const int tg = lane & 3;
  const int h = blockIdx.y;
  const int q0 = blockIdx.x * 128;
  const int colh = h * kDK;
  const size_t qrow0 = (size_t)bb * kT + q0;
  const size_t kvrow0 = (size_t)bb * kT;
  const int w16 = w * 16;

  const uint32_t smem_base = smem_u32(asm_);
  const uint32_t skb = smem_base + kOffK * 4;
  const uint32_t svb = smem_base + kOffV * 4;
  const uint32_t sqb = smem_base + kOffQ * 4;

  // ldmatrix lane constants
  const int kb_row = (lane >> 4) * 8 + (lane & 7);        // non-trans B (K)
  const int kb_col = ((lane >> 3) & 1) * 4;
  const int lm_row = ((lane >> 3) & 1) * 8 + (lane & 7);  // trans (V)
  const int lm_col = (lane >> 4) * 4;

  // stage one 128-key round into buffer buf
  auto stage_async = [&](int r, int buf) {
#pragma unroll
    for (int it = 0; it < 4; ++it) {
      int task = it * 256 + tid;  // row(7b) x granule(3b)
      int row = task >> 3;
      int gr = task & 7;
      const __half* ks = Kg + (kvrow0 + r * 128 + row) * kD + colh + gr * 8;
      const __half* vs = Vg + (kvrow0 + r * 128 + row) * kD + colh + gr * 8;
      cpa16(skb + (buf * 4608 + row * 36 + gr * 4) * 4, ks);
      cpa16(svb + (buf * 4608 + row * 36 + gr * 4) * 4, vs);
    }
    if (tid < 128)
      sBias[buf * 128 + tid] =
          mask[kvrow0 + r * 128 + tid] ? 0.f : -1.4426950e30f;
    CP_COMMIT();
  };

  // ---- stage Q (128x64) + round 0 ----
#pragma unroll
  for (int it = 0; it < 4; ++it) {
    int task = it * 256 + tid;
    int row = task >> 3;
    int gr = task & 7;
    cpa16(sqb + (row * 36 + gr * 4) * 4,
          Qg + (qrow0 + row) * kD + colh + gr * 8);
  }
  CP_COMMIT();
  stage_async(0, 0);
  CP_WAIT0();
  __syncthreads();

  // ---- lift Q A-fragments ----
  const uint32_t* sQ = asm_ + kOffQ;
  uint32_t aq[4][4];
#pragma unroll
  for (int kk = 0; kk < 4; ++kk) {
    aq[kk][0] = sQ[(w16 + g) * 36 + kk * 8 + tg];
    aq[kk][1] = sQ[(w16 + g + 8) * 36 + kk * 8 + tg];
    aq[kk][2] = sQ[(w16 + g) * 36 + kk * 8 + tg + 4];
    aq[kk][3] = sQ[(w16 + g + 8) * 36 + kk * 8 + tg + 4];
  }

  float o[8][4];
#pragma unroll
  for (int ni = 0; ni < 8; ++ni)
#pragma unroll
    for (int c = 0; c < 4; ++c) o[ni][c] = 0.f;
  float lacc[4] = {0.f, 0.f, 0.f, 0.f};
  const float sc = kSmScale * kLog2e;

  for (int r = 0; r < kNRounds; ++r) {
    const int p = r & 1;

#pragma unroll
    for (int half = 0; half < 2; ++half) {
      const uint32_t skbase = skb + (p * 4608 + half * 64 * 36) * 4;
      const uint32_t svbase = svb + (p * 4608 + half * 64 * 36) * 4;
      const float* bias = sBias + p * 128 + half * 64;

      // ---- S = Q K^T (64-key half) ----
      float s[8][4];
#pragma unroll
      for (int ni = 0; ni < 8; ++ni)
#pragma unroll
        for (int c = 0; c < 4; ++c) s[ni][c] = 0.f;
#pragma unroll
      for (int kk = 0; kk < 4; ++kk)
#pragma unroll
        for (int ni2 = 0; ni2 < 4; ++ni2) {
          uint32_t b0, b1, b2, b3;
          uint32_t addr =
              skbase + (((ni2 * 16 + kb_row) * 36) + kk * 8 + kb_col) * 4;
          ldsm4(b0, b1, b2, b3, addr);
          mma16(s[2 * ni2], aq[kk], b0, b1);
          mma16(s[2 * ni2 + 1], aq[kk], b2, b3);
        }

      // kick next round's staging once, right after the first half's S
      if (half == 0 && r + 1 < kNRounds) stage_async(r + 1, 1 - p);

      // ---- p = exp2(s*sc + bias), no max subtraction ----
#pragma unroll
      for (int ni = 0; ni < 8; ++ni) {
        float bb0 = bias[ni * 8 + 2 * tg];
        float bb1 = bias[ni * 8 + 2 * tg + 1];
        s[ni][0] = ex2(s[ni][0] * sc + bb0);
        s[ni][1] = ex2(s[ni][1] * sc + bb1);
        s[ni][2] = ex2(s[ni][2] * sc + bb0);
        s[ni][3] = ex2(s[ni][3] * sc + bb1);
      }

      // ---- O += P V ; l += P @ ones ----
#pragma unroll
      for (int kkp = 0; kkp < 4; ++kkp) {
        uint32_t pa[4];
        pa[0] = f2h2(s[2 * kkp][0], s[2 * kkp][1]);
        pa[1] = f2h2(s[2 * kkp][2], s[2 * kkp][3]);
        pa[2] = f2h2(s[2 * kkp + 1][0], s[2 * kkp + 1][1]);
        pa[3] = f2h2(s[2 * kkp + 1][2], s[2 * kkp + 1][3]);
        mma16(lacc, pa, kOnesH2, kOnesH2);
#pragma unroll
        for (int nip = 0; nip < 4; ++nip) {
          uint32_t v0, v1, v2, v3;
          uint32_t addr =
              svbase + (((16 * kkp + lm_row) * 36) + nip * 8 + lm_col) * 4;
          ldsm4t(v0, v1, v2, v3, addr);
          mma16(o[2 * nip], pa, v0, v1);
          mma16(o[2 * nip + 1], pa, v2, v3);
        }
      }
    }

    // ---- next round's copies done + visible ----
    CP_WAIT0();
    __syncthreads();
  }

  // ---- normalize, store O (fp16) ----
  const float inv0 = 1.f / lacc[0];
  const float inv1 = 1.f / lacc[2];
  uint32_t* Oh = reinterpret_cast<uint32_t*>(Og);  // half2 view
#pragma unroll
  for (int ni = 0; ni < 8; ++ni) {
    size_t idx = (qrow0 + w16 + g) * 256 + ((colh + ni * 8) >> 1) + tg;
    Oh[idx] = f2h2(o[ni][0] * inv0, o[ni][1] * inv0);
    Oh[idx + 8 * 256] = f2h2(o[ni][2] * inv1, o[ni][3] * inv1);
  }
}

// ---------------------------------------------------------------------------
extern "C" void kernel_launch(void* const* d_in, const int* in_sizes, int n_in,
                              void* d_out, int out_size) {
  const float* skel = (const float*)d_in[0];
  const float* sens = (const float*)d_in[1];
  const int* mask_skel = (const int*)d_in[2];
  const int* mask_sens = (const int*)d_in[3];
  const float* Wq_s2e = (const float*)d_in[4];
  const float* Wk_e = (const float*)d_in[5];
  const float* Wv_e = (const float*)d_in[6];
  const float* Wq_e2s = (const float*)d_in[7];
  const float* Wk_s = (const float*)d_in[8];
  const float* Wv_s = (const float*)d_in[9];
  const float* Wo_s = (const float*)d_in[10];
  const float* Wo_e = (const float*)d_in[11];

  float* out_e2s = (float*)d_out;                     // tuple element 0
  float* out_s2e = (float*)d_out + (size_t)kM * kD;   // tuple element 1

  __half *Qp, *Kp, *Vp, *Op, *Ah, *Wh;
  cudaGetSymbolAddress((void**)&Qp, g_Q);
  cudaGetSymbolAddress((void**)&Kp, g_K);
  cudaGetSymbolAddress((void**)&Vp, g_V);
  cudaGetSymbolAddress((void**)&Op, g_O);
  cudaGetSymbolAddress((void**)&Ah, g_Ah);
  cudaGetSymbolAddress((void**)&Wh, g_Wh);

  cudaFuncSetAttribute(attn_f16, cudaFuncAttributeMaxDynamicSharedMemorySize,
                       kAttnSmem);
  cudaFuncSetAttribute(gemm_h, cudaFuncAttributeMaxDynamicSharedMemorySize,
                       kGemmSmem);
  cudaFuncSetAttribute(gemm64_f32,
                       cudaFuncAttributeMaxDynamicSharedMemorySize,
                       kGemm64Smem);

  const size_t off = (size_t)kM * kD;
  const __half* skel_h = Ah;
  const __half* sens_h = Ah + off;
  auto Wp = [&](int i) { return (const __half*)(Wh + (size_t)i * kD * kD); };
  // order: 0 Wq_s2e, 1 Wk_e, 2 Wv_e, 3 Wq_e2s, 4 Wk_s, 5 Wv_s, 6 Wo_s, 7 Wo_e

  // ---- one-time conversions ----
  cvt_act<<<dim3(kM * kD / 4 / 256, 2), 256>>>(skel, sens, Ah);
  cvt_w<<<dim3(kD * kD / 4 / 256, 8), 256>>>(Wq_s2e, Wk_e, Wv_e, Wq_e2s, Wk_s,
                                             Wv_s, Wo_s, Wo_e, Wh);

  // ---- batched projections: set0 = s2e (Q,K,V), set1 = e2s (Q,K,V) ----
  Batch6 proj;
  proj.A[0] = skel_h; proj.W[0] = Wp(0); proj.C[0] = Qp;
  proj.A[1] = sens_h; proj.W[1] = Wp(1); proj.C[1] = Kp;
  proj.A[2] = sens_h; proj.W[2] = Wp(2); proj.C[2] = Vp;
  proj.A[3] = sens_h; proj.W[3] = Wp(3); proj.C[3] = Qp + off;
  proj.A[4] = skel_h; proj.W[4] = Wp(4); proj.C[4] = Kp + off;
  proj.A[5] = skel_h; proj.W[5] = Wp(5); proj.C[5] = Vp + off;
  gemm_h<<<dim3(kM / 128, kD / 128, 6), 256, kGemmSmem>>>(proj);

  // ---- batched attentions ----
  AttnBatch ab;
  ab.Q[0] = Qp;        ab.K[0] = Kp;        ab.V[0] = Vp;
  ab.M[0] = mask_sens; ab.O[0] = Op;
  ab.Q[1] = Qp + off;  ab.K[1] = Kp + off;  ab.V[1] = Vp + off;
  ab.M[1] = mask_skel; ab.O[1] = Op + off;
  attn_f16<<<dim3(kT / 128, kH, 2 * kB), 256, kAttnSmem>>>(ab);

  // ---- batched output projections (64-row tiles for tail balance) ----
  Batch2 outb;
  outb.A[0] = Op;       outb.W[0] = Wp(7); outb.C[0] = out_s2e;
  outb.A[1] = Op + off; outb.W[1] = Wp(6); outb.C[1] = out_e2s;
  gemm64_f32<<<dim3(kM / 64, kD / 128, 2), 256, kGemm64Smem>>>(outb);
}